// round 15
// baseline (speedup 1.0000x reference)
#include <cuda_runtime.h>
#include <cuda_fp16.h>
#include <cstdint>

// Sliding-window attention B=2 H=16 S=4096 D=64 W=256, non-causal, fp32 I/O.
// fp16 mma.sync flash (fp32 accumulate). Warp = 32 queries (2 m16 tiles),
// CTA = 128 queries / 4 warps, 2 CTAs/SM (255-reg budget -> max ILP:
// ptxas free to overlap s-chunk MMA/LDSM chains; K AND V prefetched at loop
// top so both DRAM latencies hide under the full contiguous compute block).
//   QK^T: m16n8k16, Q A-frags in registers, K via ldmatrix.x4
//   P·V : m16n8k16, P converts in-thread, V via ldmatrix.x4.trans
// No-max softmax (scores bounded). Interior tiles use compare-free
// packed ex2.approx.f16x2 fast path.

#define SQ 4096
#define HD 64
#define WIN 256
#define QB 128
#define NTHR 128
#define RH 72                     /* row stride in halves (144 B) */
#define T_TILE_B 9216             /* 64 * 72 * 2 bytes            */
#define V_OFF_B 18432             /* V after K double buffer      */
#define SMEM_B 36864
#define QSC 0.18033688011112042f  /* (1/8)*log2(e) */

static __device__ __forceinline__ float ex2f(float x) {
    float y; asm("ex2.approx.f32 %0, %1;" : "=f"(y) : "f"(x)); return y;
}
static __device__ __forceinline__ uint32_t h2(float a, float b) {
    __half2 h = __floats2half2_rn(a, b);
    return *(uint32_t*)&h;
}
static __device__ __forceinline__ uint32_t hex2(uint32_t x) {
    uint32_t y; asm("ex2.approx.f16x2 %0, %1;" : "=r"(y) : "r"(x)); return y;
}
static __device__ __forceinline__ uint32_t hadd2u(uint32_t a, uint32_t b) {
    uint32_t y; asm("add.f16x2 %0, %1, %2;" : "=r"(y) : "r"(a), "r"(b)); return y;
}
static __device__ __forceinline__ float2 h2f2(uint32_t w) {
    __half2 h = *(__half2*)&w;
    return __half22float2(h);
}
static __device__ __forceinline__ uint32_t smem_u32(const void* p) {
    uint32_t a;
    asm("{ .reg .u64 t; cvta.to.shared.u64 t, %1; cvt.u32.u64 %0, t; }" : "=r"(a) : "l"(p));
    return a;
}
static __device__ __forceinline__ void mma_f16(float* c, const uint32_t* a, uint32_t b0, uint32_t b1) {
    asm volatile("mma.sync.aligned.m16n8k16.row.col.f32.f16.f16.f32 "
                 "{%0,%1,%2,%3}, {%4,%5,%6,%7}, {%8,%9}, {%0,%1,%2,%3};"
                 : "+f"(c[0]), "+f"(c[1]), "+f"(c[2]), "+f"(c[3])
                 : "r"(a[0]), "r"(a[1]), "r"(a[2]), "r"(a[3]), "r"(b0), "r"(b1));
}
static __device__ __forceinline__ void ldm4(uint32_t* r, uint32_t addr) {
    asm volatile("ldmatrix.sync.aligned.m8n8.x4.shared.b16 {%0,%1,%2,%3}, [%4];"
                 : "=r"(r[0]), "=r"(r[1]), "=r"(r[2]), "=r"(r[3]) : "r"(addr));
}
static __device__ __forceinline__ void ldm4t(uint32_t* r, uint32_t addr) {
    asm volatile("ldmatrix.sync.aligned.m8n8.x4.trans.shared.b16 {%0,%1,%2,%3}, [%4];"
                 : "=r"(r[0]), "=r"(r[1]), "=r"(r[2]), "=r"(r[3]) : "r"(addr));
}
static __device__ __forceinline__ void sts64(uint32_t a, uint32_t x, uint32_t y) {
    asm volatile("st.shared.v2.b32 [%0], {%1,%2};" :: "r"(a), "r"(x), "r"(y) : "memory");
}

__global__ __launch_bounds__(NTHR, 2)
void swa_mma10(const float* __restrict__ Qg, const float* __restrict__ Kg,
               const float* __restrict__ Vg, float* __restrict__ Og)
{
    extern __shared__ __align__(16) char smem[];
    const uint32_t ksb = smem_u32(smem);
    const uint32_t vsb = ksb + V_OFF_B;

    const int tid  = threadIdx.x;
    const int w    = tid >> 5;
    const int lane = tid & 31;
    const int g    = lane >> 2;
    const int t    = lane & 3;
    const int q0   = blockIdx.x * QB;
    const size_t gb = (size_t)blockIdx.y * SQ * HD;

    const int kfirst = max(q0 - WIN, 0);
    const int klast  = min(q0 + QB - 1 + WIN, SQ - 1);
    const int NT     = (klast + 1 - kfirst) >> 6;
    const int r0     = q0 + 32 * w + g;     // warp rows: r0, r0+8, r0+16, r0+24
    const int q0w    = q0 + 32 * w;

    // ---- Q A-fragments in registers: qa[m-tile][k-chunk][4] ----
    uint32_t qa[2][4][4];
#pragma unroll
    for (int m = 0; m < 2; m++) {
        const float* Q0 = Qg + gb + (size_t)(r0 + 16 * m) * HD;
        const float* Q1 = Q0 + 8 * HD;
#pragma unroll
        for (int s = 0; s < 4; s++) {
            float2 a = *(const float2*)(Q0 + 16 * s + 2 * t);
            float2 b = *(const float2*)(Q1 + 16 * s + 2 * t);
            float2 c = *(const float2*)(Q0 + 16 * s + 2 * t + 8);
            float2 e = *(const float2*)(Q1 + 16 * s + 2 * t + 8);
            qa[m][s][0] = h2(a.x * QSC, a.y * QSC);
            qa[m][s][1] = h2(b.x * QSC, b.y * QSC);
            qa[m][s][2] = h2(c.x * QSC, c.y * QSC);
            qa[m][s][3] = h2(e.x * QSC, e.y * QSC);
        }
    }

    // ---- coalesced loader: linear float4 index i*128 + tid over the tile ----
    const float4* kg0 = (const float4*)(Kg + gb);
    const float4* vg0 = (const float4*)(Vg + gb);
    // smem scatter target for float4 #(i*128+tid): row = 8i + (tid>>4), col4 = tid&15
    const uint32_t row_b2 = (uint32_t)(((tid >> 4) * RH + (tid & 15) * 4) * 2);

    float4 kf[8], vf[8];                             // staging (both live: 2 CTAs/SM)
#define LDG8(dst, p0, kb) do {                                                \
    const float4* _p = (p0) + (size_t)(kb) * (HD / 4) + tid;                  \
    dst[0] = _p[0];   dst[1] = _p[128]; dst[2] = _p[256]; dst[3] = _p[384];   \
    dst[4] = _p[512]; dst[5] = _p[640]; dst[6] = _p[768]; dst[7] = _p[896];   \
} while (0)

#define STS8(src, tsb, bf) do {                                               \
    const float* _f = (const float*)src;                                      \
    uint32_t _a = (tsb) + (bf) * T_TILE_B + row_b2;                           \
    _Pragma("unroll")                                                         \
    for (int _i = 0; _i < 8; _i++)                                            \
        sts64(_a + _i * (8 * RH * 2),                                         \
              h2(_f[4 * _i], _f[4 * _i + 1]), h2(_f[4 * _i + 2], _f[4 * _i + 3])); \
} while (0)

    LDG8(kf, kg0, kfirst); STS8(kf, ksb, 0);
    LDG8(vf, vg0, kfirst); STS8(vf, vsb, 0);
    __syncthreads();

    float d[2][8][4];
#pragma unroll
    for (int m = 0; m < 2; m++)
#pragma unroll
        for (int j = 0; j < 8; j++)
#pragma unroll
            for (int i = 0; i < 4; i++) d[m][j][i] = 0.f;
    float lr[2][2] = {{0.f, 0.f}, {0.f, 0.f}};

    const int lj2 = (lane >> 4) & 1;
    const int lh  = (lane >> 3) & 1;
    const int lr8 = lane & 7;
    const uint32_t k_lane_h = (uint32_t)((8 * lj2 + lr8) * RH + 8 * lh);
    const uint32_t v_lane_h = (uint32_t)((8 * lh + lr8) * RH + 8 * lj2);

    int buf = 0;
    for (int tc = 0; tc < NT; tc++) {
        const int kbase = kfirst + tc * 64;
        const bool hn = (tc + 1) < NT;
        if (hn) {                                    // both prefetches at top:
            LDG8(kf, kg0, kbase + 64);               // full compute block covers
            LDG8(vf, vg0, kbase + 64);               // both DRAM latencies
        }

        if (kbase <= q0w + 31 + WIN && kbase + 63 >= q0w - WIN) {
            const bool full = (kbase >= q0w - (WIN - 31)) && (kbase <= q0w + (WIN - 63));
            const uint32_t kb_addr = ksb + (uint32_t)buf * T_TILE_B + 2u * k_lane_h;
            const uint32_t vb_addr = vsb + (uint32_t)buf * T_TILE_B + 2u * v_lane_h;

#pragma unroll
            for (int s = 0; s < 4; s++) {
                // ---- QK^T: key n-tiles 2s, 2s+1 for both m-tiles ----
                float sc[2][2][4];
#pragma unroll
                for (int m = 0; m < 2; m++)
#pragma unroll
                    for (int n = 0; n < 2; n++)
#pragma unroll
                        for (int i = 0; i < 4; i++) sc[m][n][i] = 0.f;

                const uint32_t krow = kb_addr + (uint32_t)(s * 16 * RH) * 2u;
#pragma unroll
                for (int c = 0; c < 4; c++) {
                    uint32_t kr[4];
                    ldm4(kr, krow + (uint32_t)(32 * c));
                    mma_f16(sc[0][0], qa[0][c], kr[0], kr[1]);
                    mma_f16(sc[0][1], qa[0][c], kr[2], kr[3]);
                    mma_f16(sc[1][0], qa[1][c], kr[0], kr[1]);
                    mma_f16(sc[1][1], qa[1][c], kr[2], kr[3]);
                }

                // ---- softmax: packed-f16x2 fast path or masked fp32 path ----
                uint32_t af[2][4];
                if (full) {
#pragma unroll
                    for (int m = 0; m < 2; m++) {
                        af[m][0] = hex2(h2(sc[m][0][0], sc[m][0][1]));
                        af[m][1] = hex2(h2(sc[m][0][2], sc[m][0][3]));
                        af[m][2] = hex2(h2(sc[m][1][0], sc[m][1][1]));
                        af[m][3] = hex2(h2(sc[m][1][2], sc[m][1][3]));
                        float2 f02 = h2f2(hadd2u(af[m][0], af[m][2]));
                        float2 f13 = h2f2(hadd2u(af[m][1], af[m][3]));
                        lr[m][0] += f02.x + f02.y;
                        lr[m][1] += f13.x + f13.y;
                    }
                } else {
                    const int kc0 = kbase + 16 * s + 2 * t;
#pragma unroll
                    for (int m = 0; m < 2; m++) {
                        const int rm = r0 + 16 * m;
                        float p00 = ((unsigned)(kc0      - rm + WIN)       <= 2u * WIN) ? ex2f(sc[m][0][0]) : 0.f;
                        float p01 = ((unsigned)(kc0 + 1  - rm + WIN)       <= 2u * WIN) ? ex2f(sc[m][0][1]) : 0.f;
                        float p02 = ((unsigned)(kc0      - (rm + 8) + WIN) <= 2u * WIN) ? ex2f(sc[m][0][2]) : 0.f;
                        float p03 = ((unsigned)(kc0 + 1  - (rm + 8) + WIN) <= 2u * WIN) ? ex2f(sc[m][0][3]) : 0.f;
                        float p10 = ((unsigned)(kc0 + 8  - rm + WIN)       <= 2u * WIN) ? ex2f(sc[m][1][0]) : 0.f;
                        float p11 = ((unsigned)(kc0 + 9  - rm + WIN)       <= 2u * WIN) ? ex2f(sc[m][1][1]) : 0.f;
                        float p12 = ((unsigned)(kc0 + 8  - (rm + 8) + WIN) <= 2u * WIN) ? ex2f(sc[m][1][2]) : 0.f;
                        float p13 = ((unsigned)(kc0 + 9  - (rm + 8) + WIN) <= 2u * WIN) ? ex2f(sc[m][1][3]) : 0.f;
                        lr[m][0] += (p00 + p01) + (p10 + p11);
                        lr[m][1] += (p02 + p03) + (p12 + p13);
                        af[m][0] = h2(p00, p01);
                        af[m][1] = h2(p02, p03);
                        af[m][2] = h2(p10, p11);
                        af[m][3] = h2(p12, p13);
                    }
                }

                // ---- P·V: V B-frags via ldmatrix.trans, shared by both m ----
                const uint32_t vrow = vb_addr + (uint32_t)(s * 16 * RH) * 2u;
#pragma unroll
                for (int jp = 0; jp < 4; jp++) {
                    uint32_t vr[4];
                    ldm4t(vr, vrow + (uint32_t)(32 * jp));
                    mma_f16(d[0][2 * jp],     af[0], vr[0], vr[1]);
                    mma_f16(d[0][2 * jp + 1], af[0], vr[2], vr[3]);
                    mma_f16(d[1][2 * jp],     af[1], vr[0], vr[1]);
                    mma_f16(d[1][2 * jp + 1], af[1], vr[2], vr[3]);
                }
            }
        }

        if (hn) {
            STS8(kf, ksb, buf ^ 1);                  // commit K(t+1)
            STS8(vf, vsb, buf ^ 1);                  // commit V(t+1)
        }
        __syncthreads();
        buf ^= 1;
    }

    // ---- epilogue: quad-reduce l, normalize, store ----
#pragma unroll
    for (int m = 0; m < 2; m++)
#pragma unroll
        for (int i = 0; i < 2; i++) {
            lr[m][i] += __shfl_xor_sync(0xffffffffu, lr[m][i], 1);
            lr[m][i] += __shfl_xor_sync(0xffffffffu, lr[m][i], 2);
            lr[m][i] = 1.0f / lr[m][i];
        }

#pragma unroll
    for (int m = 0; m < 2; m++) {
        float* o0 = Og + gb + (size_t)(r0 + 16 * m) * HD;
        float* o1 = o0 + 8 * HD;
#pragma unroll
        for (int j = 0; j < 8; j++) {
            float2 a, b;
            a.x = d[m][j][0] * lr[m][0]; a.y = d[m][j][1] * lr[m][0];
            b.x = d[m][j][2] * lr[m][1]; b.y = d[m][j][3] * lr[m][1];
            *(float2*)(o0 + 8 * j + 2 * t) = a;
            *(float2*)(o1 + 8 * j + 2 * t) = b;
        }
    }
}

extern "C" void kernel_launch(void* const* d_in, const int* in_sizes, int n_in,
                              void* d_out, int out_size)
{
    (void)in_sizes; (void)n_in; (void)out_size;
    cudaFuncSetAttribute(swa_mma10, cudaFuncAttributeMaxDynamicSharedMemorySize, SMEM_B);
    dim3 grid(SQ / QB, 32);
    swa_mma10<<<grid, NTHR, SMEM_B>>>((const float*)d_in[0], (const float*)d_in[1],
                                      (const float*)d_in[2], (float*)d_out);
}

// round 16
// speedup vs baseline: 1.0431x; 1.0431x over previous
#include <cuda_runtime.h>
#include <cuda_fp16.h>
#include <cstdint>

// Sliding-window attention B=2 H=16 S=4096 D=64 W=256, non-causal, fp32 I/O.
// fp16 mma.sync flash (fp32 accumulate). Warp = 32 queries (2 m16 tiles),
// CTA = 128 queries / 4 warps, 3 CTAs/SM (R14 base — proven fastest).
//   QK^T: m16n8k16, Q A-frags in registers, K via ldmatrix.x4
//   P·V : m16n8k16, P converts in-thread, V via ldmatrix.x4.trans
// K/V global loads coalesced; all tile memory ops clustered at loop end.
// No-max softmax (scores bounded). BOTH softmax paths use packed
// ex2.approx.f16x2 (masked path selects score or -1e4 pre-pack; fp16 exp
// underflows to exactly 0, preserving the band mask).

#define SQ 4096
#define HD 64
#define WIN 256
#define QB 128
#define NTHR 128
#define RH 72                     /* row stride in halves (144 B) */
#define T_TILE_B 9216             /* 64 * 72 * 2 bytes            */
#define V_OFF_B 18432             /* V after K double buffer      */
#define SMEM_B 36864
#define QSC 0.18033688011112042f  /* (1/8)*log2(e) */

static __device__ __forceinline__ uint32_t h2(float a, float b) {
    __half2 h = __floats2half2_rn(a, b);
    return *(uint32_t*)&h;
}
static __device__ __forceinline__ uint32_t hex2(uint32_t x) {
    uint32_t y; asm("ex2.approx.f16x2 %0, %1;" : "=r"(y) : "r"(x)); return y;
}
static __device__ __forceinline__ uint32_t hadd2u(uint32_t a, uint32_t b) {
    uint32_t y; asm("add.f16x2 %0, %1, %2;" : "=r"(y) : "r"(a), "r"(b)); return y;
}
static __device__ __forceinline__ float2 h2f2(uint32_t w) {
    __half2 h = *(__half2*)&w;
    return __half22float2(h);
}
static __device__ __forceinline__ uint32_t smem_u32(const void* p) {
    uint32_t a;
    asm("{ .reg .u64 t; cvta.to.shared.u64 t, %1; cvt.u32.u64 %0, t; }" : "=r"(a) : "l"(p));
    return a;
}
static __device__ __forceinline__ void mma_f16(float* c, const uint32_t* a, uint32_t b0, uint32_t b1) {
    asm volatile("mma.sync.aligned.m16n8k16.row.col.f32.f16.f16.f32 "
                 "{%0,%1,%2,%3}, {%4,%5,%6,%7}, {%8,%9}, {%0,%1,%2,%3};"
                 : "+f"(c[0]), "+f"(c[1]), "+f"(c[2]), "+f"(c[3])
                 : "r"(a[0]), "r"(a[1]), "r"(a[2]), "r"(a[3]), "r"(b0), "r"(b1));
}
static __device__ __forceinline__ void ldm4(uint32_t* r, uint32_t addr) {
    asm volatile("ldmatrix.sync.aligned.m8n8.x4.shared.b16 {%0,%1,%2,%3}, [%4];"
                 : "=r"(r[0]), "=r"(r[1]), "=r"(r[2]), "=r"(r[3]) : "r"(addr));
}
static __device__ __forceinline__ void ldm4t(uint32_t* r, uint32_t addr) {
    asm volatile("ldmatrix.sync.aligned.m8n8.x4.trans.shared.b16 {%0,%1,%2,%3}, [%4];"
                 : "=r"(r[0]), "=r"(r[1]), "=r"(r[2]), "=r"(r[3]) : "r"(addr));
}
static __device__ __forceinline__ void sts64(uint32_t a, uint32_t x, uint32_t y) {
    asm volatile("st.shared.v2.b32 [%0], {%1,%2};" :: "r"(a), "r"(x), "r"(y) : "memory");
}

__global__ __launch_bounds__(NTHR, 3)
void swa_mma11(const float* __restrict__ Qg, const float* __restrict__ Kg,
               const float* __restrict__ Vg, float* __restrict__ Og)
{
    extern __shared__ __align__(16) char smem[];
    const uint32_t ksb = smem_u32(smem);
    const uint32_t vsb = ksb + V_OFF_B;

    const int tid  = threadIdx.x;
    const int w    = tid >> 5;
    const int lane = tid & 31;
    const int g    = lane >> 2;
    const int t    = lane & 3;
    const int q0   = blockIdx.x * QB;
    const size_t gb = (size_t)blockIdx.y * SQ * HD;

    const int kfirst = max(q0 - WIN, 0);
    const int klast  = min(q0 + QB - 1 + WIN, SQ - 1);
    const int NT     = (klast + 1 - kfirst) >> 6;
    const int r0     = q0 + 32 * w + g;     // warp rows: r0, r0+8, r0+16, r0+24
    const int q0w    = q0 + 32 * w;

    // ---- Q A-fragments in registers: qa[m-tile][k-chunk][4] ----
    uint32_t qa[2][4][4];
#pragma unroll
    for (int m = 0; m < 2; m++) {
        const float* Q0 = Qg + gb + (size_t)(r0 + 16 * m) * HD;
        const float* Q1 = Q0 + 8 * HD;
#pragma unroll
        for (int s = 0; s < 4; s++) {
            float2 a = *(const float2*)(Q0 + 16 * s + 2 * t);
            float2 b = *(const float2*)(Q1 + 16 * s + 2 * t);
            float2 c = *(const float2*)(Q0 + 16 * s + 2 * t + 8);
            float2 e = *(const float2*)(Q1 + 16 * s + 2 * t + 8);
            qa[m][s][0] = h2(a.x * QSC, a.y * QSC);
            qa[m][s][1] = h2(b.x * QSC, b.y * QSC);
            qa[m][s][2] = h2(c.x * QSC, c.y * QSC);
            qa[m][s][3] = h2(e.x * QSC, e.y * QSC);
        }
    }

    // ---- coalesced loader: linear float4 index i*128 + tid over the tile ----
    const float4* kg0 = (const float4*)(Kg + gb);
    const float4* vg0 = (const float4*)(Vg + gb);
    // smem scatter target for float4 #(i*128+tid): row = 8i + (tid>>4), col4 = tid&15
    const uint32_t row_b2 = (uint32_t)(((tid >> 4) * RH + (tid & 15) * 4) * 2);

    float4 pf[8];                                    // staging (K or V)
#define LDG8(p0, kb) do {                                                     \
    const float4* _p = (p0) + (size_t)(kb) * (HD / 4) + tid;                  \
    pf[0] = _p[0];   pf[1] = _p[128]; pf[2] = _p[256]; pf[3] = _p[384];       \
    pf[4] = _p[512]; pf[5] = _p[640]; pf[6] = _p[768]; pf[7] = _p[896];       \
} while (0)

#define STS8(tsb, bf) do {                                                    \
    const float* _f = (const float*)pf;                                       \
    uint32_t _a = (tsb) + (bf) * T_TILE_B + row_b2;                           \
    _Pragma("unroll")                                                         \
    for (int _i = 0; _i < 8; _i++)                                            \
        sts64(_a + _i * (8 * RH * 2),                                         \
              h2(_f[4 * _i], _f[4 * _i + 1]), h2(_f[4 * _i + 2], _f[4 * _i + 3])); \
} while (0)

    LDG8(kg0, kfirst); STS8(ksb, 0);
    LDG8(vg0, kfirst); STS8(vsb, 0);
    __syncthreads();

    float d[2][8][4];
#pragma unroll
    for (int m = 0; m < 2; m++)
#pragma unroll
        for (int j = 0; j < 8; j++)
#pragma unroll
            for (int i = 0; i < 4; i++) d[m][j][i] = 0.f;
    float lr[2][2] = {{0.f, 0.f}, {0.f, 0.f}};

    const int lj2 = (lane >> 4) & 1;
    const int lh  = (lane >> 3) & 1;
    const int lr8 = lane & 7;
    const uint32_t k_lane_h = (uint32_t)((8 * lj2 + lr8) * RH + 8 * lh);
    const uint32_t v_lane_h = (uint32_t)((8 * lh + lr8) * RH + 8 * lj2);

    const float MK = -1.0e4f;                        // exp2 underflows fp16 -> 0

    int buf = 0;
    for (int tc = 0; tc < NT; tc++) {
        const int kbase = kfirst + tc * 64;
        const bool hn = (tc + 1) < NT;
        if (hn) LDG8(kg0, kbase + 64);               // K(t+1) in flight

        if (kbase <= q0w + 31 + WIN && kbase + 63 >= q0w - WIN) {
            const bool full = (kbase >= q0w - (WIN - 31)) && (kbase <= q0w + (WIN - 63));
            const uint32_t kb_addr = ksb + (uint32_t)buf * T_TILE_B + 2u * k_lane_h;
            const uint32_t vb_addr = vsb + (uint32_t)buf * T_TILE_B + 2u * v_lane_h;

#pragma unroll
            for (int s = 0; s < 4; s++) {
                // ---- QK^T: key n-tiles 2s, 2s+1 for both m-tiles ----
                float sc[2][2][4];
#pragma unroll
                for (int m = 0; m < 2; m++)
#pragma unroll
                    for (int n = 0; n < 2; n++)
#pragma unroll
                        for (int i = 0; i < 4; i++) sc[m][n][i] = 0.f;

                const uint32_t krow = kb_addr + (uint32_t)(s * 16 * RH) * 2u;
#pragma unroll
                for (int c = 0; c < 4; c++) {
                    uint32_t kr[4];
                    ldm4(kr, krow + (uint32_t)(32 * c));
                    mma_f16(sc[0][0], qa[0][c], kr[0], kr[1]);
                    mma_f16(sc[0][1], qa[0][c], kr[2], kr[3]);
                    mma_f16(sc[1][0], qa[1][c], kr[0], kr[1]);
                    mma_f16(sc[1][1], qa[1][c], kr[2], kr[3]);
                }

                // ---- softmax: packed f16x2 exp in BOTH paths ----
                uint32_t af[2][4];
                if (!full) {
                    // mask by selecting score or -1e4 before the packed exp
                    const int kc0 = kbase + 16 * s + 2 * t;
#pragma unroll
                    for (int m = 0; m < 2; m++) {
                        const int rm = r0 + 16 * m;
                        sc[m][0][0] = ((unsigned)(kc0      - rm + WIN)       <= 2u * WIN) ? sc[m][0][0] : MK;
                        sc[m][0][1] = ((unsigned)(kc0 + 1  - rm + WIN)       <= 2u * WIN) ? sc[m][0][1] : MK;
                        sc[m][0][2] = ((unsigned)(kc0      - (rm + 8) + WIN) <= 2u * WIN) ? sc[m][0][2] : MK;
                        sc[m][0][3] = ((unsigned)(kc0 + 1  - (rm + 8) + WIN) <= 2u * WIN) ? sc[m][0][3] : MK;
                        sc[m][1][0] = ((unsigned)(kc0 + 8  - rm + WIN)       <= 2u * WIN) ? sc[m][1][0] : MK;
                        sc[m][1][1] = ((unsigned)(kc0 + 9  - rm + WIN)       <= 2u * WIN) ? sc[m][1][1] : MK;
                        sc[m][1][2] = ((unsigned)(kc0 + 8  - (rm + 8) + WIN) <= 2u * WIN) ? sc[m][1][2] : MK;
                        sc[m][1][3] = ((unsigned)(kc0 + 9  - (rm + 8) + WIN) <= 2u * WIN) ? sc[m][1][3] : MK;
                    }
                }
#pragma unroll
                for (int m = 0; m < 2; m++) {
                    af[m][0] = hex2(h2(sc[m][0][0], sc[m][0][1]));
                    af[m][1] = hex2(h2(sc[m][0][2], sc[m][0][3]));
                    af[m][2] = hex2(h2(sc[m][1][0], sc[m][1][1]));
                    af[m][3] = hex2(h2(sc[m][1][2], sc[m][1][3]));
                    float2 f02 = h2f2(hadd2u(af[m][0], af[m][2]));
                    float2 f13 = h2f2(hadd2u(af[m][1], af[m][3]));
                    lr[m][0] += f02.x + f02.y;
                    lr[m][1] += f13.x + f13.y;
                }

                // ---- P·V: V B-frags via ldmatrix.trans, shared by both m ----
                const uint32_t vrow = vb_addr + (uint32_t)(s * 16 * RH) * 2u;
#pragma unroll
                for (int jp = 0; jp < 4; jp++) {
                    uint32_t vr[4];
                    ldm4t(vr, vrow + (uint32_t)(32 * jp));
                    mma_f16(d[0][2 * jp],     af[0], vr[0], vr[1]);
                    mma_f16(d[0][2 * jp + 1], af[0], vr[2], vr[3]);
                    mma_f16(d[1][2 * jp],     af[1], vr[0], vr[1]);
                    mma_f16(d[1][2 * jp + 1], af[1], vr[2], vr[3]);
                }
            }
        }

        if (hn) {
            STS8(ksb, buf ^ 1);                      // commit K(t+1)
            LDG8(vg0, kbase + 64);                   // V(t+1): short-lead load
            STS8(vsb, buf ^ 1);                      // commit V(t+1)
        }
        __syncthreads();
        buf ^= 1;
    }

    // ---- epilogue: quad-reduce l, normalize, store ----
#pragma unroll
    for (int m = 0; m < 2; m++)
#pragma unroll
        for (int i = 0; i < 2; i++) {
            lr[m][i] += __shfl_xor_sync(0xffffffffu, lr[m][i], 1);
            lr[m][i] += __shfl_xor_sync(0xffffffffu, lr[m][i], 2);
            lr[m][i] = 1.0f / lr[m][i];
        }

#pragma unroll
    for (int m = 0; m < 2; m++) {
        float* o0 = Og + gb + (size_t)(r0 + 16 * m) * HD;
        float* o1 = o0 + 8 * HD;
#pragma unroll
        for (int j = 0; j < 8; j++) {
            float2 a, b;
            a.x = d[m][j][0] * lr[m][0]; a.y = d[m][j][1] * lr[m][0];
            b.x = d[m][j][2] * lr[m][1]; b.y = d[m][j][3] * lr[m][1];
            *(float2*)(o0 + 8 * j + 2 * t) = a;
            *(float2*)(o1 + 8 * j + 2 * t) = b;
        }
    }
}

extern "C" void kernel_launch(void* const* d_in, const int* in_sizes, int n_in,
                              void* d_out, int out_size)
{
    (void)in_sizes; (void)n_in; (void)out_size;
    cudaFuncSetAttribute(swa_mma11, cudaFuncAttributeMaxDynamicSharedMemorySize, SMEM_B);
    dim3 grid(SQ / QB, 32);
    swa_mma11<<<grid, NTHR, SMEM_B>>>((const float*)d_in[0], (const float*)d_in[1],
                                      (const float*)d_in[2], (float*)d_out);
}